// round 7
// baseline (speedup 1.0000x reference)
#include <cuda_runtime.h>
#include <cstddef>

// 7x7 VALID conv, 4096x4096 fp32 -> 4090x4090 fp32, + bias.
// Block 16x16 = 256 threads; tile 128(w) x 32(h); thread: 2 rows x 8 cols.
// Weight-pair FFMA2 scheme: each output j has ONE packed accumulator whose two
// halves are partial sums of that output (out[j] = lo + hi). All FFMA2 data
// operands are even-aligned pairs E[v] straight from LDS.128 -> zero repacking.
//   even j=2v:  acc += E[v+t] * P[t],  P = (w0,w1)(w2,w3)(w4,w5)(w6,0)
//   odd  j=2v+1: acc += E[v+t] * Q[t], Q = (0,w0)(w1,w2)(w3,w4)(w5,w6)
// Tile is stored with the SW128 XOR swizzle so the 32B-stride LDS.128 pattern
// is bank-conflict-free.

#define IN_W 4096
#define IN_H 4096
#define OUT_W 4090
#define OUT_H 4090

#define TILE_W 128
#define TILE_H 32
#define SM_H (TILE_H + 6)   // 38
#define SM_W 136            // 134 needed, padded to /4

typedef unsigned long long u64;

__device__ __forceinline__ u64 pk(float a, float b) {
    u64 r;
    asm("mov.b64 %0, {%1, %2};" : "=l"(r) : "f"(a), "f"(b));
    return r;
}
__device__ __forceinline__ void upk(u64 v, float &a, float &b) {
    asm("mov.b64 {%0, %1}, %2;" : "=f"(a), "=f"(b) : "l"(v));
}
__device__ __forceinline__ void fma2(u64 &d, u64 a, u64 b) {
    asm("fma.rn.f32x2 %0, %1, %2, %3;" : "=l"(d) : "l"(a), "l"(b), "l"(d));
}

__device__ __forceinline__ unsigned sw128(unsigned b) {
    return b ^ ((b >> 3) & 0x70u);
}

__global__ __launch_bounds__(256, 3)
void conv7x7_kernel(const float* __restrict__ x,
                    const float* __restrict__ w,
                    const float* __restrict__ bias,
                    float* __restrict__ out)
{
    __shared__ float tile[SM_H * SM_W];     // swizzled storage
    __shared__ u64   wp[7][8];              // per row: P0 P2 P4 P6 Q0 Q1 Q3 Q5
    __shared__ float bs;

    const int tx = threadIdx.x;         // 0..15
    const int ty = threadIdx.y;         // 0..15
    const int tid = ty * 16 + tx;       // 0..255

    const int bx = blockIdx.x * TILE_W;
    const int by = blockIdx.y * TILE_H;

    if (tid < 7) {
        const float* wr = w + tid * 7;
        float w0 = wr[0], w1 = wr[1], w2 = wr[2], w3 = wr[3],
              w4 = wr[4], w5 = wr[5], w6 = wr[6];
        wp[tid][0] = pk(w0, w1);
        wp[tid][1] = pk(w2, w3);
        wp[tid][2] = pk(w4, w5);
        wp[tid][3] = pk(w6, 0.f);
        wp[tid][4] = pk(0.f, w0);
        wp[tid][5] = pk(w1, w2);
        wp[tid][6] = pk(w3, w4);
        wp[tid][7] = pk(w5, w6);
    }
    if (tid == 7) bs = bias[0];

    // ---- Load input tile (38 x 136 floats, float4, swizzled stores) ----
    #pragma unroll 1
    for (int i = tid; i < SM_H * (SM_W / 4); i += 256) {
        const int r  = i / (SM_W / 4);
        const int c4 = i - r * (SM_W / 4);
        const int gy = by + r;
        const int gx = bx + c4 * 4;
        float4 v = make_float4(0.f, 0.f, 0.f, 0.f);
        if (gy < IN_H) {
            const float* row = x + (size_t)gy * IN_W;
            if (gx + 4 <= IN_W) {
                v = *reinterpret_cast<const float4*>(row + gx);
            } else if (gx < IN_W) {
                v.x = row[gx];
                if (gx + 1 < IN_W) v.y = row[gx + 1];
                if (gx + 2 < IN_W) v.z = row[gx + 2];
            }
        }
        const unsigned b = (unsigned)(r * SM_W + c4 * 4) * 4u;
        *reinterpret_cast<float4*>(
            reinterpret_cast<char*>(tile) + sw128(b)) = v;
    }
    __syncthreads();

    // ---- Compute: 2 output rows x 8 cols per thread ----
    const int tx8 = tx * 8;
    const int ry  = ty * 2;

    // acc[ar][j], j=0..7: packed partials of single output (lo+hi = out)
    u64 acc[2][8];
    #pragma unroll
    for (int a = 0; a < 2; a++)
        #pragma unroll
        for (int j = 0; j < 8; j++) acc[a][j] = 0ull;

    #pragma unroll
    for (int r = 0; r < 8; r++) {
        // E[m] = (seg[2m], seg[2m+1]), m=0..7 via 4 swizzled LDS.128
        u64 E[8];
        {
            const unsigned base = (unsigned)((ry + r) * SM_W + tx8) * 4u;
            #pragma unroll
            for (int k = 0; k < 4; k++) {
                ulonglong2 q = *reinterpret_cast<const ulonglong2*>(
                    reinterpret_cast<const char*>(tile) + sw128(base + 16u * k));
                E[2 * k]     = q.x;
                E[2 * k + 1] = q.y;
            }
        }

        #pragma unroll
        for (int ar = 0; ar < 2; ar++) {
            const int kr = r - ar;
            if (kr >= 0 && kr <= 6) {
                u64 P[4], Q[4];
                {
                    const ulonglong2* w2p =
                        reinterpret_cast<const ulonglong2*>(&wp[kr][0]);
                    ulonglong2 a0 = w2p[0], a1 = w2p[1],
                               a2 = w2p[2], a3 = w2p[3];
                    P[0] = a0.x; P[1] = a0.y; P[2] = a1.x; P[3] = a1.y;
                    Q[0] = a2.x; Q[1] = a2.y; Q[2] = a3.x; Q[3] = a3.y;
                }
                #pragma unroll
                for (int v = 0; v < 4; v++) {
                    #pragma unroll
                    for (int t = 0; t < 4; t++) {
                        fma2(acc[ar][2 * v],     E[v + t], P[t]);
                        fma2(acc[ar][2 * v + 1], E[v + t], Q[t]);
                    }
                }
            }
        }
    }

    // ---- Epilogue: out[j] = acc.lo + acc.hi + bias; float2 stores ----
    const float bv = bs;
    #pragma unroll
    for (int ar = 0; ar < 2; ar++) {
        const int oy = by + ry + ar;
        if (oy < OUT_H) {
            float* orow = out + (size_t)oy * OUT_W;
            #pragma unroll
            for (int v = 0; v < 4; v++) {
                const int ox = bx + tx8 + 2 * v;
                if (ox < OUT_W) {
                    float l0, h0, l1, h1;
                    upk(acc[ar][2 * v],     l0, h0);
                    upk(acc[ar][2 * v + 1], l1, h1);
                    float2 o;
                    o.x = l0 + h0 + bv;
                    o.y = l1 + h1 + bv;
                    *reinterpret_cast<float2*>(orow + ox) = o;
                }
            }
        }
    }
}

extern "C" void kernel_launch(void* const* d_in, const int* in_sizes, int n_in,
                              void* d_out, int out_size)
{
    const float* x    = (const float*)d_in[0];
    const float* w    = (const float*)d_in[1];
    const float* bias = (const float*)d_in[2];
    float* out = (float*)d_out;

    dim3 block(16, 16);
    dim3 grid((OUT_W + TILE_W - 1) / TILE_W,   // 32
              (OUT_H + TILE_H - 1) / TILE_H);  // 128
    conv7x7_kernel<<<grid, block>>>(x, w, bias, out);
}

// round 8
// speedup vs baseline: 1.3755x; 1.3755x over previous
#include <cuda_runtime.h>
#include <cstddef>

// 7x7 VALID conv, 4096x4096 fp32 -> 4090x4090 fp32, + bias.
// Block 16x8 = 128 threads; tile 128(w) x 32(h); thread: 4 rows x 8 cols.
// Packed fma.rn.f32x2, single accumulator family (24.5 fma2/out).
// Odd-tap pairs S[m] = (seg[2m+1], seg[2m+2]) built with exactly 2 MOVs each
// via float aliases of the E registers (no inline-asm unpack chains).
// __launch_bounds__(128, 8) pins regs<=64 -> ~32 warps/SM.

#define IN_W 4096
#define IN_H 4096
#define OUT_W 4090
#define OUT_H 4090

#define TILE_W 128
#define TILE_H 32
#define SM_H (TILE_H + 6)   // 38
#define SM_W 136            // 134 needed, padded (544B rows, 16B aligned)

typedef unsigned long long u64;

__device__ __forceinline__ u64 pk(float a, float b) {
    u64 r;
    asm("mov.b64 %0, {%1, %2};" : "=l"(r) : "f"(a), "f"(b));
    return r;
}
__device__ __forceinline__ void fma2(u64 &d, u64 a, u64 b) {
    asm("fma.rn.f32x2 %0, %1, %2, %3;" : "=l"(d) : "l"(a), "l"(b), "l"(d));
}
__device__ __forceinline__ u64 add2(u64 a, u64 b) {
    u64 r;
    asm("add.rn.f32x2 %0, %1, %2;" : "=l"(r) : "l"(a), "l"(b));
    return r;
}

__global__ __launch_bounds__(128, 8)
void conv7x7_kernel(const float* __restrict__ x,
                    const float* __restrict__ w,
                    const float* __restrict__ bias,
                    float* __restrict__ out)
{
    __shared__ float tile[SM_H][SM_W];
    __shared__ u64   wp[7][8];      // weight rows (w,w) pairs, padded to 64B
    __shared__ float bs;

    const int tx = threadIdx.x;     // 0..15
    const int ty = threadIdx.y;     // 0..7
    const int tid = ty * 16 + tx;   // 0..127

    const int bx = blockIdx.x * TILE_W;
    const int by = blockIdx.y * TILE_H;

    if (tid < 49) {
        const int r = tid / 7, c = tid % 7;
        float wv = w[tid];
        wp[r][c] = pk(wv, wv);
    }
    if (tid == 49) bs = bias[0];

    // ---- Load input tile (38 x 136 floats, float4 granularity) ----
    #pragma unroll 1
    for (int i = tid; i < SM_H * (SM_W / 4); i += 128) {
        const int r  = i / (SM_W / 4);
        const int c4 = i - r * (SM_W / 4);
        const int gy = by + r;
        const int gx = bx + c4 * 4;
        float4 v = make_float4(0.f, 0.f, 0.f, 0.f);
        if (gy < IN_H) {
            const float* row = x + (size_t)gy * IN_W;
            if (gx + 4 <= IN_W) {
                v = *reinterpret_cast<const float4*>(row + gx);
            } else if (gx < IN_W) {
                v.x = row[gx];
                if (gx + 1 < IN_W) v.y = row[gx + 1];
                if (gx + 2 < IN_W) v.z = row[gx + 2];
            }
        }
        *reinterpret_cast<float4*>(&tile[r][c4 * 4]) = v;
    }
    __syncthreads();

    // ---- Compute: 4 output rows x 8 cols per thread ----
    const int tx8 = tx * 8;         // col base (32B-aligned in smem)
    const int ry  = ty * 4;         // first output row within tile

    // acc[ar][v] = (out[2v], out[2v+1]) for output row ry+ar
    u64 acc[4][4];
    #pragma unroll
    for (int a = 0; a < 4; a++)
        #pragma unroll
        for (int v = 0; v < 4; v++) acc[a][v] = 0ull;

    #pragma unroll
    for (int r = 0; r < 10; r++) {
        // E[m] = (seg[2m], seg[2m+1]), m=0..6
        u64 E[7];
        {
            const ulonglong2* s2 =
                reinterpret_cast<const ulonglong2*>(&tile[ry + r][tx8]);
            ulonglong2 q0 = s2[0];
            ulonglong2 q1 = s2[1];
            ulonglong2 q2 = s2[2];
            E[0] = q0.x; E[1] = q0.y;
            E[2] = q1.x; E[3] = q1.y;
            E[4] = q2.x; E[5] = q2.y;
            E[6] = *reinterpret_cast<const u64*>(&tile[ry + r][tx8 + 12]);
        }
        // S[m] = (seg[2m+1], seg[2m+2]) from float aliases: 2 MOVs each
        const float* ef = reinterpret_cast<const float*>(E);
        u64 S[6];
        #pragma unroll
        for (int m = 0; m < 6; m++)
            S[m] = pk(ef[2 * m + 1], ef[2 * m + 2]);

        #pragma unroll
        for (int ar = 0; ar < 4; ar++) {
            const int kr = r - ar;
            if (kr >= 0 && kr <= 6) {
                // weight row kr: 3x LDS.128 + 1x LDS.64, broadcast
                u64 wr[7];
                {
                    const ulonglong2* w2 =
                        reinterpret_cast<const ulonglong2*>(&wp[kr][0]);
                    ulonglong2 a0 = w2[0];
                    ulonglong2 a1 = w2[1];
                    ulonglong2 a2 = w2[2];
                    wr[0] = a0.x; wr[1] = a0.y;
                    wr[2] = a1.x; wr[3] = a1.y;
                    wr[4] = a2.x; wr[5] = a2.y;
                    wr[6] = wp[kr][6];
                }
                // even taps
                #pragma unroll
                for (int dx = 0; dx <= 6; dx += 2) {
                    #pragma unroll
                    for (int v = 0; v < 4; v++)
                        fma2(acc[ar][v], E[v + dx / 2], wr[dx]);
                }
                // odd taps
                #pragma unroll
                for (int dx = 1; dx <= 5; dx += 2) {
                    #pragma unroll
                    for (int v = 0; v < 4; v++)
                        fma2(acc[ar][v], S[v + (dx - 1) / 2], wr[dx]);
                }
            }
        }
    }

    // ---- Epilogue: packed bias add, 8B stores ----
    const float bv = bs;
    const u64 bp = pk(bv, bv);
    #pragma unroll
    for (int ar = 0; ar < 4; ar++) {
        const int oy = by + ry + ar;
        if (oy < OUT_H) {
            float* orow = out + (size_t)oy * OUT_W;
            #pragma unroll
            for (int v = 0; v < 4; v++) {
                const int ox = bx + tx8 + 2 * v;
                if (ox < OUT_W) {
                    u64 o = add2(acc[ar][v], bp);
                    *reinterpret_cast<u64*>(orow + ox) = o;
                }
            }
        }
    }
}

extern "C" void kernel_launch(void* const* d_in, const int* in_sizes, int n_in,
                              void* d_out, int out_size)
{
    const float* x    = (const float*)d_in[0];
    const float* w    = (const float*)d_in[1];
    const float* bias = (const float*)d_in[2];
    float* out = (float*)d_out;

    dim3 block(16, 8);
    dim3 grid((OUT_W + TILE_W - 1) / TILE_W,   // 32
              (OUT_H + TILE_H - 1) / TILE_H);  // 128
    conv7x7_kernel<<<grid, block>>>(x, w, bias, out);
}